// round 2
// baseline (speedup 1.0000x reference)
#include <cuda_runtime.h>
#include <math.h>
#include <cstdint>

// Problem constants
#define E_TOTAL  160000
#define NNODES   10000
#define TE1      32      // rows per block, kernel 1
#define TE2      64      // edges per block, kernel 2

#define INV_SQRT3 0.5773502691896258f
#define ALPHA     0.17677669529663687f   // 1/sqrt(32)

typedef unsigned long long ull;

// Scratch (device globals: no allocation allowed)
__device__ float g_h[(size_t)E_TOTAL * 128];   // gelu(emb@W1+b1), 82 MB
__device__ float g_cnt[NNODES];

// ---------------------------------------------------------------------------
// packed f32x2 helpers (Blackwell): ptxas won't auto-fuse, must use PTX
// ---------------------------------------------------------------------------
__device__ __forceinline__ ull ffma2(ull a, ull b, ull c) {
    ull d;
    asm("fma.rn.f32x2 %0, %1, %2, %3;" : "=l"(d) : "l"(a), "l"(b), "l"(c));
    return d;
}
__device__ __forceinline__ ull pack2(float x, float y) {
    return (ull)__float_as_uint(x) | ((ull)__float_as_uint(y) << 32);
}
__device__ __forceinline__ float lo2(ull a) { return __uint_as_float((unsigned)a); }
__device__ __forceinline__ float hi2(ull a) { return __uint_as_float((unsigned)(a >> 32)); }

__device__ __forceinline__ float gelu_exact(float x) {
    return 0.5f * x * (1.0f + erff(x * 0.7071067811865476f));
}

// ---------------------------------------------------------------------------
// Kernel 0: zero output accumulator + counts
// ---------------------------------------------------------------------------
__global__ void k_zero(float* __restrict__ out) {
    int i = blockIdx.x * blockDim.x + threadIdx.x;
    if (i < NNODES * 64) out[i] = 0.0f;
    if (i < NNODES) g_cnt[i] = 0.0f;
}

// ---------------------------------------------------------------------------
// Kernel 1: h = gelu(emb @ W1 + b1)   [160000 x 128] = [.. x128]@[128x128]
// Block: 32 rows, 256 threads. W1 fully staged in smem (64 KB).
// Thread (r = tid>>3, u = tid&7) owns cols {4u + 32i + j : i<4, j<4}
// -> per LDS.128 instruction lanes hit banks 4u..4u+3: conflict-free.
// ---------------------------------------------------------------------------
__global__ void __launch_bounds__(256)
k_mlp1(const float* __restrict__ emb, const float* __restrict__ W1,
       const float* __restrict__ b1) {
    extern __shared__ float smem[];
    float* W1s  = smem;               // 128*128
    float* embs = smem + 128 * 128;   // 32*128
    int tid = threadIdx.x;
    size_t rowBase = (size_t)blockIdx.x * TE1;

    {   // stage W1 (coalesced)
        const float4* Wv = (const float4*)W1;
        float4* Wsv = (float4*)W1s;
#pragma unroll
        for (int it = 0; it < 16; it++) Wsv[it * 256 + tid] = Wv[it * 256 + tid];
        // stage emb tile
        const float4* ev = (const float4*)(emb + rowBase * 128);
        float4* esv = (float4*)embs;
#pragma unroll
        for (int it = 0; it < 4; it++) esv[it * 256 + tid] = ev[it * 256 + tid];
    }
    __syncthreads();

    int r = tid >> 3;
    int u = tid & 7;
    ull acc[8];
#pragma unroll
    for (int i = 0; i < 4; i++) {
        const float* bp = b1 + 4 * u + 32 * i;
        acc[2 * i]     = pack2(__ldg(bp + 0), __ldg(bp + 1));
        acc[2 * i + 1] = pack2(__ldg(bp + 2), __ldg(bp + 3));
    }
    const float* hrow = embs + r * 128;
#pragma unroll 4
    for (int k = 0; k < 128; k++) {
        float hv = hrow[k];
        ull hp = pack2(hv, hv);
        const float* wr = W1s + k * 128;
#pragma unroll
        for (int i = 0; i < 4; i++) {
            ulonglong2 wv = *(const ulonglong2*)(wr + 4 * u + 32 * i);
            acc[2 * i]     = ffma2(hp, wv.x, acc[2 * i]);
            acc[2 * i + 1] = ffma2(hp, wv.y, acc[2 * i + 1]);
        }
    }
    float* outp = g_h + (rowBase + r) * 128;
#pragma unroll
    for (int i = 0; i < 4; i++) {
        float4 o;
        o.x = gelu_exact(lo2(acc[2 * i]));
        o.y = gelu_exact(hi2(acc[2 * i]));
        o.z = gelu_exact(lo2(acc[2 * i + 1]));
        o.w = gelu_exact(hi2(acc[2 * i + 1]));
        *(float4*)(outp + 4 * u + 32 * i) = o;
    }
}

// ---------------------------------------------------------------------------
// TP shuffle-reduction: acc (8 ull = 16 fp32 cols of this thread),
// coefficient vector c16[u_tp], reduce over u_tp, lanes with usub==0 write
// the 4 w' values of their group into r16.
// Thread col mapping: col_local = 4u + 64i + j  ->  u_tp = 4i + (u>>2),
// w' = (u&3)*4 + j.  Reduction over u_tp = in-thread over i + xor-shfl 4,8.
// ---------------------------------------------------------------------------
__device__ __forceinline__ void tp_reduce(const ull* acc, const float* c16,
                                          float* r16, int usub, int wq, bool add) {
    float p0 = 0.f, p1 = 0.f, p2 = 0.f, p3 = 0.f;
#pragma unroll
    for (int i = 0; i < 4; i++) {
        float cu = c16[4 * i + usub];
        p0 = fmaf(cu, lo2(acc[2 * i]), p0);
        p1 = fmaf(cu, hi2(acc[2 * i]), p1);
        p2 = fmaf(cu, lo2(acc[2 * i + 1]), p2);
        p3 = fmaf(cu, hi2(acc[2 * i + 1]), p3);
    }
    p0 += __shfl_xor_sync(0xffffffffu, p0, 4);
    p1 += __shfl_xor_sync(0xffffffffu, p1, 4);
    p2 += __shfl_xor_sync(0xffffffffu, p2, 4);
    p3 += __shfl_xor_sync(0xffffffffu, p3, 4);
    p0 += __shfl_xor_sync(0xffffffffu, p0, 8);
    p1 += __shfl_xor_sync(0xffffffffu, p1, 8);
    p2 += __shfl_xor_sync(0xffffffffu, p2, 8);
    p3 += __shfl_xor_sync(0xffffffffu, p3, 8);
    if (usub == 0) {
        float* d = r16 + wq * 4;
        if (add) { d[0] += p0; d[1] += p1; d[2] += p2; d[3] += p3; }
        else     { d[0]  = p0; d[1]  = p1; d[2]  = p2; d[3]  = p3; }
    }
}

// ---------------------------------------------------------------------------
// Kernel 2: fused GEMM2 (h @ W2 + b2) + tensor product + atomic scatter.
// Block: 64 edges, 256 threads. Loops the 4 weight "types" (256-col chunks),
// staging W2 in 32k x 256n smem tiles. Thread (u = tid&15, rg = tid>>4)
// computes 16 cols for 4 edges {rg, rg+16, rg+32, rg+48}.
// ---------------------------------------------------------------------------
__global__ void __launch_bounds__(256)
k_fused(const float* __restrict__ xfeat, const float* __restrict__ esh,
        const float* __restrict__ W2, const float* __restrict__ b2,
        const int* __restrict__ src, const int* __restrict__ dstp,
        float* __restrict__ out) {
    extern __shared__ float smem[];
    float* h_s  = smem;               // 64*128 = 8192
    float* w2s  = h_s + 8192;         // 32*256 = 8192
    float* c0s  = w2s + 8192;         // 64*16
    float* c1s  = c0s + 1024;
    float* c2s  = c1s + 1024;
    float* c3s  = c2s + 1024;         // 64*48 ([e][m][u])
    float* r0s  = c3s + 3072;         // 64*16
    float* r2s  = r0s + 1024;
    float* r3s  = r2s + 1024;         // 64*48 ([e][m][w'])
    float* sh1s = r3s + 3072;         // 64*4
    int*   dsts = (int*)(sh1s + 256); // 64

    int tid = threadIdx.x;
    int eBase = blockIdx.x * TE2;

    {   // stage h tile (coalesced)
        const float4* hv = (const float4*)(g_h + (size_t)eBase * 128);
        float4* hsv = (float4*)h_s;
#pragma unroll
        for (int it = 0; it < 8; it++) hsv[it * 256 + tid] = hv[it * 256 + tid];
    }
    {   // per-edge TP coefficients: 4 threads/edge, 4 u each
        int e  = tid >> 2;
        int ge = eBase + e;
        int u0 = (tid & 3) * 4;
        int si = __ldg(src + ge);
        const float* x   = xfeat + (size_t)si * 64;
        const float* shp = esh + (size_t)ge * 4;
        float sh0 = __ldg(shp + 0);
        float s1x = __ldg(shp + 1), s1y = __ldg(shp + 2), s1z = __ldg(shp + 3);
#pragma unroll
        for (int du = 0; du < 4; du++) {
            int u = u0 + du;
            float s  = __ldg(x + u);
            float v0 = __ldg(x + 16 + 3 * u);
            float v1 = __ldg(x + 17 + 3 * u);
            float v2 = __ldg(x + 18 + 3 * u);
            c0s[e * 16 + u] = sh0 * s;
            c1s[e * 16 + u] = INV_SQRT3 * (v0 * s1x + v1 * s1y + v2 * s1z);
            c2s[e * 16 + u] = s;
            c3s[e * 48 + 0 * 16 + u] = sh0 * v0;
            c3s[e * 48 + 1 * 16 + u] = sh0 * v1;
            c3s[e * 48 + 2 * 16 + u] = sh0 * v2;
        }
        if ((tid & 3) == 0) {
            dsts[e] = __ldg(dstp + ge);
            sh1s[e * 4 + 0] = s1x; sh1s[e * 4 + 1] = s1y; sh1s[e * 4 + 2] = s1z;
        }
    }

    int u    = tid & 15;
    int rg   = tid >> 4;
    int usub = u >> 2;
    int wq   = u & 3;
    const float* hrow0 = h_s + (rg +  0) * 128;
    const float* hrow1 = h_s + (rg + 16) * 128;
    const float* hrow2 = h_s + (rg + 32) * 128;
    const float* hrow3 = h_s + (rg + 48) * 128;

#pragma unroll
    for (int t = 0; t < 4; t++) {
        ull acc[4][8];
#pragma unroll
        for (int i = 0; i < 4; i++) {   // init with bias (same for all edges)
            const float* bp = b2 + t * 256 + (u + 16 * i) * 4;
            ull blo = pack2(__ldg(bp + 0), __ldg(bp + 1));
            ull bhi = pack2(__ldg(bp + 2), __ldg(bp + 3));
#pragma unroll
            for (int s = 0; s < 4; s++) { acc[s][2 * i] = blo; acc[s][2 * i + 1] = bhi; }
        }
        for (int k0 = 0; k0 < 128; k0 += 32) {
            __syncthreads();
            {   // stage W2[k0..k0+32, t*256..t*256+256]
                const float4* wv = (const float4*)(W2 + (size_t)k0 * 1024 + t * 256);
                float4* wsv = (float4*)w2s;
#pragma unroll
                for (int it = 0; it < 8; it++) {
                    int idx = it * 256 + tid;
                    int row = idx >> 6;
                    int c4  = idx & 63;
                    wsv[row * 64 + c4] = wv[row * 256 + c4];
                }
            }
            __syncthreads();
#pragma unroll 4
            for (int kk = 0; kk < 32; kk++) {
                float h0 = hrow0[k0 + kk], h1 = hrow1[k0 + kk];
                float h2 = hrow2[k0 + kk], h3 = hrow3[k0 + kk];
                ull hp0 = pack2(h0, h0), hp1 = pack2(h1, h1);
                ull hp2 = pack2(h2, h2), hp3 = pack2(h3, h3);
                const float* wr = w2s + kk * 256;
#pragma unroll
                for (int i = 0; i < 4; i++) {
                    ulonglong2 wv = *(const ulonglong2*)(wr + (u + 16 * i) * 4);
                    acc[0][2 * i]     = ffma2(hp0, wv.x, acc[0][2 * i]);
                    acc[0][2 * i + 1] = ffma2(hp0, wv.y, acc[0][2 * i + 1]);
                    acc[1][2 * i]     = ffma2(hp1, wv.x, acc[1][2 * i]);
                    acc[1][2 * i + 1] = ffma2(hp1, wv.y, acc[1][2 * i + 1]);
                    acc[2][2 * i]     = ffma2(hp2, wv.x, acc[2][2 * i]);
                    acc[2][2 * i + 1] = ffma2(hp2, wv.y, acc[2][2 * i + 1]);
                    acc[3][2 * i]     = ffma2(hp3, wv.x, acc[3][2 * i]);
                    acc[3][2 * i + 1] = ffma2(hp3, wv.y, acc[3][2 * i + 1]);
                }
            }
        }
        // TP contraction of this 256-col chunk (uniform control flow per warp)
        if (t == 0) {
#pragma unroll
            for (int s = 0; s < 4; s++) {
                int e = rg + 16 * s;
                tp_reduce(acc[s], c0s + e * 16, r0s + e * 16, usub, wq, false);
            }
        } else if (t == 1) {
#pragma unroll
            for (int s = 0; s < 4; s++) {
                int e = rg + 16 * s;
                tp_reduce(acc[s], c1s + e * 16, r0s + e * 16, usub, wq, true);
            }
        } else if (t == 2) {
#pragma unroll
            for (int s = 0; s < 4; s++) {
                int e = rg + 16 * s;
                tp_reduce(acc[s], c2s + e * 16, r2s + e * 16, usub, wq, false);
            }
        } else {
#pragma unroll
            for (int m = 0; m < 3; m++) {
#pragma unroll
                for (int s = 0; s < 4; s++) {
                    int e = rg + 16 * s;
                    tp_reduce(acc[s], c3s + e * 48 + m * 16, r3s + e * 48 + m * 16,
                              usub, wq, false);
                }
            }
        }
    }
    __syncthreads();

    {   // combine + atomic scatter: 16 outputs per thread
        int e  = tid >> 2;
        int jb = (tid & 3) * 16;
        int d  = dsts[e];
        float* op = out + (size_t)d * 64;
        if (jb == 0) {
#pragma unroll
            for (int j = 0; j < 16; j++)
                atomicAdd(op + j, ALPHA * r0s[e * 16 + j]);
            atomicAdd(&g_cnt[d], 1.0f);
        } else {
#pragma unroll
            for (int jj = 0; jj < 16; jj++) {
                int q  = jb - 16 + jj;     // 0..47
                int wp = q / 3;
                int m  = q - 3 * wp;
                float val = ALPHA * (sh1s[e * 4 + m] * r2s[e * 16 + wp] +
                                     r3s[e * 48 + m * 16 + wp]);
                atomicAdd(op + 16 + q, val);
            }
        }
    }
}

// ---------------------------------------------------------------------------
// Kernel 3: segment mean normalization
// ---------------------------------------------------------------------------
__global__ void k_norm(float* __restrict__ out) {
    int i = blockIdx.x * blockDim.x + threadIdx.x;
    if (i < NNODES * 64) {
        float c = g_cnt[i >> 6];
        out[i] = out[i] / fmaxf(c, 1.0f);
    }
}

// ---------------------------------------------------------------------------
extern "C" void kernel_launch(void* const* d_in, const int* in_sizes, int n_in,
                              void* d_out, int out_size) {
    const float* xfeat = (const float*)d_in[0];  // src_features (10000,64)
    const float* eshv  = (const float*)d_in[1];  // edge_sh (160000,4)
    const float* emb   = (const float*)d_in[2];  // edge_emb (160000,128)
    const float* W1    = (const float*)d_in[3];  // (128,128)
    const float* b1    = (const float*)d_in[4];  // (128,)
    const float* W2    = (const float*)d_in[5];  // (128,1024)
    const float* b2    = (const float*)d_in[6];  // (1024,)
    const int*   src   = (const int*)d_in[7];    // (160000,)
    const int*   dstp  = (const int*)d_in[8];    // (160000,)
    float* out = (float*)d_out;                  // (10000,64) f32

    const int SMEM1 = (128 * 128 + TE1 * 128) * 4;                     // 81920
    const int SMEM2 = (8192 + 8192 + 1024 * 3 + 3072 + 1024 * 2 + 3072 + 256) * 4
                      + 64 * 4;                                        // ~109.3 KB
    cudaFuncSetAttribute(k_mlp1, cudaFuncAttributeMaxDynamicSharedMemorySize, SMEM1);
    cudaFuncSetAttribute(k_fused, cudaFuncAttributeMaxDynamicSharedMemorySize, SMEM2);

    k_zero<<<(NNODES * 64 + 255) / 256, 256>>>(out);
    k_mlp1<<<E_TOTAL / TE1, 256, SMEM1>>>(emb, W1, b1);
    k_fused<<<E_TOTAL / TE2, 256, SMEM2>>>(xfeat, eshv, W2, b2, src, dstp, out);
    k_norm<<<(NNODES * 64 + 255) / 256, 256>>>(out);
}